// round 16
// baseline (speedup 1.0000x reference)
#include <cuda_runtime.h>
#include <cuda_bf16.h>
#include <stdint.h>

#define S_LEN 1024
#define HD    64
#define BM    128            // Q rows per CTA (4 warps x 32 rows)
#define BN    64             // KV rows per tile
#define QTILES (S_LEN / BM)  // 8
#define KTILES (S_LEN / BN)  // 16
#define NB    128

// work decomposition: 1024 (b,qtile) pairs = 888 full CTAs + 136 pairs
// split into 272 half-KV CTAs (tail-wave filling). 888 = 296*3 = 444*2.
#define FULL_CTAS  888
#define TAIL_PAIRS 136

// ---------------- device scratch (no cudaMalloc allowed) ----------------
#define KV_U4 ((size_t)NB * S_LEN * HD / 8)
__device__ uint4 g_khi[KV_U4];
__device__ uint4 g_klo[KV_U4];
__device__ uint4 g_vhi[KV_U4];
__device__ uint4 g_vlo[KV_U4];
// split-KV partials: 272 half-results of [128 rows][64 cols] + row sums
__device__ float g_po [(size_t)2 * TAIL_PAIRS * BM * HD];
__device__ float g_prs[(size_t)2 * TAIL_PAIRS * BM];

// ---------------- helpers ----------------
__device__ __forceinline__ uint32_t smem_u32(const void* p) {
    uint32_t a;
    asm("{ .reg .u64 t; cvta.to.shared.u64 t, %1; cvt.u32.u64 %0, t; }"
        : "=r"(a) : "l"(p));
    return a;
}

__device__ __forceinline__ void split2(float a, float b, uint32_t& h, uint32_t& l) {
    __nv_bfloat162 H = __floats2bfloat162_rn(a, b);
    float ra = a - __bfloat162float(H.x);
    float rb = b - __bfloat162float(H.y);
    __nv_bfloat162 L = __floats2bfloat162_rn(ra, rb);
    h = *(uint32_t*)&H;
    l = *(uint32_t*)&L;
}

__device__ __forceinline__ float ex2f(float x) {
    float y;
    asm("ex2.approx.f32 %0, %1;" : "=f"(y) : "f"(x));
    return y;
}

#define LDSM4(r0, r1, r2, r3, addr) \
    asm volatile("ldmatrix.sync.aligned.m8n8.x4.shared.b16 {%0,%1,%2,%3}, [%4];" \
                 : "=r"(r0), "=r"(r1), "=r"(r2), "=r"(r3) : "r"(addr))

#define LDSM4T(r0, r1, r2, r3, addr) \
    asm volatile("ldmatrix.sync.aligned.m8n8.x4.trans.shared.b16 {%0,%1,%2,%3}, [%4];" \
                 : "=r"(r0), "=r"(r1), "=r"(r2), "=r"(r3) : "r"(addr))

#define MMA16816(c, a, b0, b1) \
    asm volatile("mma.sync.aligned.m16n8k16.row.col.f32.bf16.bf16.f32 " \
                 "{%0,%1,%2,%3}, {%4,%5,%6,%7}, {%8,%9}, {%0,%1,%2,%3};" \
                 : "+f"((c)[0]), "+f"((c)[1]), "+f"((c)[2]), "+f"((c)[3]) \
                 : "r"((a)[0]), "r"((a)[1]), "r"((a)[2]), "r"((a)[3]), \
                   "r"(b0), "r"(b1))

#define CP16(sm, gp)  asm volatile("cp.async.cg.shared.global [%0], [%1], 16;" :: "r"(sm), "l"(gp))
#define CP_COMMIT()   asm volatile("cp.async.commit_group;" ::: "memory")
#define CP_WAIT(n)    asm volatile("cp.async.wait_group %0;" :: "n"(n) : "memory")

// ---------------- pre-kernel: bf16 hi/lo split of K and V ----------------
__global__ __launch_bounds__(256)
void presplit_kernel(const float* __restrict__ k, const float* __restrict__ v) {
    const float4* k4 = (const float4*)k;
    const float4* v4 = (const float4*)v;
    uint2* kh = (uint2*)g_khi;
    uint2* kl = (uint2*)g_klo;
    uint2* vh = (uint2*)g_vhi;
    uint2* vl = (uint2*)g_vlo;
    const size_t n4 = (size_t)NB * S_LEN * HD / 4;
    for (size_t i = (size_t)blockIdx.x * 256 + threadIdx.x; i < n4;
         i += (size_t)gridDim.x * 256) {
        float4 x = k4[i];
        uint2 H, L;
        split2(x.x, x.y, H.x, L.x);
        split2(x.z, x.w, H.y, L.y);
        kh[i] = H; kl[i] = L;
        x = v4[i];
        split2(x.x, x.y, H.x, L.x);
        split2(x.z, x.w, H.y, L.y);
        vh[i] = H; vl[i] = L;
    }
}

// ---------------- main kernel ----------------
// smem: double-buffered KV tile set. Each buffer: KH,KL,VH,VL of
// [64 rows][72 bf16] (64 data + 8 pad), 144 B/row -> 9216 B per component.
#define COMPB 9216
#define BUFB  (4 * COMPB)        // 36864
#define KH2 0
#define KL2 (1 * COMPB)
#define VH2 (2 * COMPB)
#define VL2 (3 * COMPB)
#define SMEM_TOTAL (2 * BUFB)    // 73728 -> 2 CTAs/SM

// stage one 64-row KV tile (4 components) via cp.async: 16 x 16B per thread
__device__ __forceinline__ void issue_tile(uint32_t sbuf,
                                           const uint4* kh, const uint4* kl,
                                           const uint4* vh, const uint4* vl, int tid) {
    #pragma unroll
    for (int i = 0; i < 4; i++) {
        int f = tid + i * 128;                       // 0..511 = row*8 + colgroup
        uint32_t off = (uint32_t)(f >> 3) * 144 + (f & 7) * 16;
        CP16(sbuf + KH2 + off, kh + f);
        CP16(sbuf + KL2 + off, kl + f);
        CP16(sbuf + VH2 + off, vh + f);
        CP16(sbuf + VL2 + off, vl + f);
    }
}

__global__ __launch_bounds__(128, 2)
void mea_mma_kernel(const float* __restrict__ q, float* __restrict__ out) {
    extern __shared__ char sc[];
    const uint32_t sb = smem_u32(sc);
    const int tid  = threadIdx.x;
    const int lane = tid & 31;
    const int w    = tid >> 5;            // warp 0..3 -> Q rows 32w..32w+31
    const int gid  = lane >> 2;
    const int tig  = lane & 3;
    const int bid  = blockIdx.x;

    // ---- work assignment: full pair or half-KV tail slice ----
    int pid, t0, t1, sci;
    if (bid < FULL_CTAS) {
        pid = bid;  t0 = 0;  t1 = KTILES;  sci = -1;
    } else {
        const int i = bid - FULL_CTAS;       // 0..271
        pid = FULL_CTAS + (i >> 1);
        const int h = i & 1;
        t0 = h * (KTILES / 2);  t1 = t0 + KTILES / 2;  sci = i;
    }
    const int rmask = (t1 - t0) - 1;
    const int b  = pid >> 3;                 // QTILES = 8
    const int qi = pid & 7;
    const int q0 = qi * BM;

    // ---- stage+split Q (128x64 fp32, scaled by log2e) in two 64-row passes,
    //      through buffer 0's KH/KL areas; hoist A-fragments to registers ----
    uint32_t qh[2][4][4], ql[2][4][4];    // [m16 group][kc][frag]
    {
        const float L2E = 1.4426950408889634f;
        #pragma unroll 1
        for (int p = 0; p < 2; p++) {
            const float4* qg4 =
                (const float4*)(q + ((size_t)b * S_LEN + q0 + p * 64) * HD);
            #pragma unroll
            for (int i = 0; i < 4; i++) {
                int f8 = tid + i * 128;           // row*8 + colgroup, row < 64
                float4 x = qg4[2 * f8], y = qg4[2 * f8 + 1];
                uint4 H, L;
                split2(x.x * L2E, x.y * L2E, H.x, L.x);
                split2(x.z * L2E, x.w * L2E, H.y, L.y);
                split2(y.x * L2E, y.y * L2E, H.z, L.z);
                split2(y.z * L2E, y.w * L2E, H.w, L.w);
                uint32_t off = (uint32_t)(f8 >> 3) * 144 + (f8 & 7) * 16;
                *(uint4*)(sc + KH2 + off) = H;
                *(uint4*)(sc + KL2 + off) = L;
            }
            __syncthreads();
            if ((w >> 1) == p) {                   // warps whose rows are staged
                const uint32_t aQ = sb + KH2
                    + (uint32_t)((w & 1) * 32 + (lane & 15)) * 144
                    + ((lane >> 4) & 1) * 16;
                #pragma unroll
                for (int g = 0; g < 2; g++)
                    #pragma unroll
                    for (int kc = 0; kc < 4; kc++) {
                        LDSM4(qh[g][kc][0], qh[g][kc][1], qh[g][kc][2], qh[g][kc][3],
                              aQ + g * 16 * 144 + kc * 32);
                        LDSM4(ql[g][kc][0], ql[g][kc][1], ql[g][kc][2], ql[g][kc][3],
                              aQ + COMPB + g * 16 * 144 + kc * 32);
                    }
            }
            __syncthreads();                       // staging read before reuse
        }
    }

    const uint4* khB = g_khi + (size_t)b * S_LEN * 8;
    const uint4* klB = g_klo + (size_t)b * S_LEN * 8;
    const uint4* vhB = g_vhi + (size_t)b * S_LEN * 8;
    const uint4* vlB = g_vlo + (size_t)b * S_LEN * 8;

    // prefetch tiles t0 and t0+1 into the two buffers
    issue_tile(sb, khB + (size_t)t0 * 512, klB + (size_t)t0 * 512,
               vhB + (size_t)t0 * 512, vlB + (size_t)t0 * 512, tid);
    CP_COMMIT();
    issue_tile(sb + BUFB, khB + (size_t)(t0 + 1) * 512, klB + (size_t)(t0 + 1) * 512,
               vhB + (size_t)(t0 + 1) * 512, vlB + (size_t)(t0 + 1) * 512, tid);
    CP_COMMIT();

    float o[2][8][4];
    #pragma unroll
    for (int g = 0; g < 2; g++)
        #pragma unroll
        for (int d = 0; d < 8; d++)
            #pragma unroll
            for (int j = 0; j < 4; j++) o[g][d][j] = 0.0f;
    float rs[2][2] = {{0.0f, 0.0f}, {0.0f, 0.0f}};

    #pragma unroll 1
    for (int t = t0; t < t1; t++) {
        const uint32_t bufo = (uint32_t)(t & 1) * BUFB;

        CP_WAIT(1);          // tile t's cp.async group complete
        __syncthreads();     // ...and visible to all threads

        const uint32_t bK = sb + bufo + KH2
            + (uint32_t)((lane & 7) + ((lane >> 4) & 1) * 8) * 144
            + ((lane >> 3) & 1) * 16;
        const uint32_t bV = sb + bufo + VH2
            + (uint32_t)((lane & 7) + ((lane >> 3) & 1) * 8) * 144
            + ((lane >> 4) & 1) * 16;

        // ---- S = Q K^T, 3xBF16; each B fragment feeds both m16 groups ----
        float s[2][8][4];
        #pragma unroll
        for (int g = 0; g < 2; g++)
            #pragma unroll
            for (int np = 0; np < 8; np++)
                #pragma unroll
                for (int j = 0; j < 4; j++) s[g][np][j] = 0.0f;

        #pragma unroll
        for (int kc = 0; kc < 4; kc++)
            #pragma unroll
            for (int grp = 0; grp < 4; grp++) {   // 16-key groups
                uint32_t bh[4], bl[4];
                LDSM4(bh[0], bh[1], bh[2], bh[3], bK + grp * 2304 + kc * 32);
                LDSM4(bl[0], bl[1], bl[2], bl[3], bK + COMPB + grp * 2304 + kc * 32);
                #pragma unroll
                for (int g = 0; g < 2; g++) {
                    MMA16816(s[g][2*grp],   qh[g][kc], bh[0], bh[1]);
                    MMA16816(s[g][2*grp+1], qh[g][kc], bh[2], bh[3]);
                    MMA16816(s[g][2*grp],   qh[g][kc], bl[0], bl[1]);
                    MMA16816(s[g][2*grp+1], qh[g][kc], bl[2], bl[3]);
                    MMA16816(s[g][2*grp],   ql[g][kc], bh[0], bh[1]);
                    MMA16816(s[g][2*grp+1], ql[g][kc], bh[2], bh[3]);
                }
            }

        // ---- exp (Q pre-scaled -> ex2) + row sums + split (s dies here) ----
        uint32_t ph[2][4][4], pl[2][4][4];
        #pragma unroll
        for (int g = 0; g < 2; g++)
            #pragma unroll
            for (int kc = 0; kc < 4; kc++) {
                float a0 = ex2f(s[g][2*kc][0]),   a1 = ex2f(s[g][2*kc][1]);
                float a2 = ex2f(s[g][2*kc][2]),   a3 = ex2f(s[g][2*kc][3]);
                float b0 = ex2f(s[g][2*kc+1][0]), b1 = ex2f(s[g][2*kc+1][1]);
                float b2 = ex2f(s[g][2*kc+1][2]), b3 = ex2f(s[g][2*kc+1][3]);
                rs[g][0] += a0 + a1 + b0 + b1;
                rs[g][1] += a2 + a3 + b2 + b3;
                split2(a0, a1, ph[g][kc][0], pl[g][kc][0]);
                split2(a2, a3, ph[g][kc][1], pl[g][kc][1]);
                split2(b0, b1, ph[g][kc][2], pl[g][kc][2]);
                split2(b2, b3, ph[g][kc][3], pl[g][kc][3]);
            }

        // ---- O += P V, 3xBF16; each V fragment feeds both m16 groups ----
        #pragma unroll
        for (int kc = 0; kc < 4; kc++)
            #pragma unroll
            for (int np = 0; np < 4; np++) {      // d16 groups
                uint32_t vh[4], vl[4];
                LDSM4T(vh[0], vh[1], vh[2], vh[3], bV + kc * 2304 + np * 32);
                LDSM4T(vl[0], vl[1], vl[2], vl[3], bV + COMPB + kc * 2304 + np * 32);
                #pragma unroll
                for (int g = 0; g < 2; g++) {
                    MMA16816(o[g][2*np],   ph[g][kc], vh[0], vh[1]);
                    MMA16816(o[g][2*np+1], ph[g][kc], vh[2], vh[3]);
                    MMA16816(o[g][2*np],   ph[g][kc], vl[0], vl[1]);
                    MMA16816(o[g][2*np+1], ph[g][kc], vl[2], vl[3]);
                    MMA16816(o[g][2*np],   pl[g][kc], vh[0], vh[1]);
                    MMA16816(o[g][2*np+1], pl[g][kc], vh[2], vh[3]);
                }
            }

        __syncthreads();     // all warps done reading this buffer
        const int tn = t0 + ((t - t0 + 2) & rmask);
        issue_tile(sb + bufo, khB + (size_t)tn * 512, klB + (size_t)tn * 512,
                   vhB + (size_t)tn * 512, vlB + (size_t)tn * 512, tid);
        CP_COMMIT();
    }

    CP_WAIT(0);   // drain trailing (wrapped) prefetches before CTA exit

    // ---- epilogue: quad-reduce 4 row sums ----
    #pragma unroll
    for (int g = 0; g < 2; g++)
        #pragma unroll
        for (int j = 0; j < 2; j++) {
            rs[g][j] += __shfl_xor_sync(0xffffffffu, rs[g][j], 1);
            rs[g][j] += __shfl_xor_sync(0xffffffffu, rs[g][j], 2);
        }

    if (sci < 0) {
        // full pair: normalize and write out
        #pragma unroll
        for (int g = 0; g < 2; g++) {
            const float i0 = 1.0f / rs[g][0];
            const float i1 = 1.0f / rs[g][1];
            float* orow = out + ((size_t)b * S_LEN + q0 + w * 32 + g * 16 + gid) * HD;
            #pragma unroll
            for (int d = 0; d < 8; d++) {
                *(float2*)(orow + d * 8 + 2 * tig) =
                    make_float2(o[g][d][0] * i0, o[g][d][1] * i0);
                *(float2*)(orow + 8 * HD + d * 8 + 2 * tig) =
                    make_float2(o[g][d][2] * i1, o[g][d][3] * i1);
            }
        }
    } else {
        // half slice: write unnormalized partial O + row sums to scratch
        #pragma unroll
        for (int g = 0; g < 2; g++) {
            float* prow = g_po + ((size_t)sci * BM + w * 32 + g * 16 + gid) * HD;
            #pragma unroll
            for (int d = 0; d < 8; d++) {
                *(float2*)(prow + d * 8 + 2 * tig) =
                    make_float2(o[g][d][0], o[g][d][1]);
                *(float2*)(prow + 8 * HD + d * 8 + 2 * tig) =
                    make_float2(o[g][d][2], o[g][d][3]);
            }
            if (tig == 0) {
                g_prs[(size_t)sci * BM + w * 32 + g * 16 + gid]     = rs[g][0];
                g_prs[(size_t)sci * BM + w * 32 + g * 16 + 8 + gid] = rs[g][1];
            }
        }
    }
}

// ---------------- combine kernel: sum split-KV halves, normalize ----------------
__global__ __launch_bounds__(128)
void combine_kernel(float* __restrict__ out) {
    const int i   = blockIdx.x;          // 0..TAIL_PAIRS-1
    const int row = threadIdx.x;         // 0..127
    const int pid = FULL_CTAS + i;
    const int b   = pid >> 3;
    const int qi  = pid & 7;

    const float rsum = g_prs[(size_t)(2 * i) * BM + row]
                     + g_prs[(size_t)(2 * i + 1) * BM + row];
    const float inv = 1.0f / rsum;

    const float4* p0 = (const float4*)(g_po + ((size_t)(2 * i)     * BM + row) * HD);
    const float4* p1 = (const float4*)(g_po + ((size_t)(2 * i + 1) * BM + row) * HD);
    float4* orow = (float4*)(out + ((size_t)b * S_LEN + qi * BM + row) * HD);
    #pragma unroll
    for (int c = 0; c < HD / 4; c++) {
        float4 a = p0[c], d = p1[c];
        orow[c] = make_float4((a.x + d.x) * inv, (a.y + d.y) * inv,
                              (a.z + d.z) * inv, (a.w + d.w) * inv);
    }
}

// ---------------- launch ----------------
extern "C" void kernel_launch(void* const* d_in, const int* in_sizes, int n_in,
                              void* d_out, int out_size)
{
    const float* q = (const float*)d_in[0];
    const float* k = (const float*)d_in[1];
    const float* v = (const float*)d_in[2];
    float* out = (float*)d_out;

    cudaFuncSetAttribute(mea_mma_kernel,
                         cudaFuncAttributeMaxDynamicSharedMemorySize, SMEM_TOTAL);

    presplit_kernel<<<2048, 256>>>(k, v);
    mea_mma_kernel<<<FULL_CTAS + 2 * TAIL_PAIRS, 128, SMEM_TOTAL>>>(q, out);
    combine_kernel<<<TAIL_PAIRS, 128>>>(out);
}

// round 17
// speedup vs baseline: 1.0014x; 1.0014x over previous
#include <cuda_runtime.h>
#include <cuda_bf16.h>
#include <stdint.h>

#define S_LEN 1024
#define HD    64
#define BM    128            // Q rows per CTA (4 warps x 32 rows)
#define BN    64             // KV rows per tile
#define QTILES (S_LEN / BM)  // 8
#define KTILES (S_LEN / BN)  // 16
#define NB    128

// decomposition: 1024 (b,qtile) pairs = 888 full CTAs (3 exact waves at
// 2 CTAs/SM on 148 SMs) + 136 pairs split into 272 half-KV CTAs (1 short wave).
#define FULL_CTAS  888
#define TAIL_PAIRS 136

// ---------------- device scratch (no cudaMalloc allowed) ----------------
#define KV_U4 ((size_t)NB * S_LEN * HD / 8)
__device__ uint4 g_khi[KV_U4];
__device__ uint4 g_klo[KV_U4];
__device__ uint4 g_vhi[KV_U4];
__device__ uint4 g_vlo[KV_U4];
__device__ float g_po [(size_t)2 * TAIL_PAIRS * BM * HD];
__device__ float g_prs[(size_t)2 * TAIL_PAIRS * BM];

// ---------------- helpers ----------------
__device__ __forceinline__ uint32_t smem_u32(const void* p) {
    uint32_t a;
    asm("{ .reg .u64 t; cvta.to.shared.u64 t, %1; cvt.u32.u64 %0, t; }"
        : "=r"(a) : "l"(p));
    return a;
}

__device__ __forceinline__ void split2(float a, float b, uint32_t& h, uint32_t& l) {
    __nv_bfloat162 H = __floats2bfloat162_rn(a, b);
    float ra = a - __bfloat162float(H.x);
    float rb = b - __bfloat162float(H.y);
    __nv_bfloat162 L = __floats2bfloat162_rn(ra, rb);
    h = *(uint32_t*)&H;
    l = *(uint32_t*)&L;
}

__device__ __forceinline__ float ex2f(float x) {
    float y;
    asm("ex2.approx.f32 %0, %1;" : "=f"(y) : "f"(x));
    return y;
}

#define LDSM4(r0, r1, r2, r3, addr) \
    asm volatile("ldmatrix.sync.aligned.m8n8.x4.shared.b16 {%0,%1,%2,%3}, [%4];" \
                 : "=r"(r0), "=r"(r1), "=r"(r2), "=r"(r3) : "r"(addr))

#define LDSM4T(r0, r1, r2, r3, addr) \
    asm volatile("ldmatrix.sync.aligned.m8n8.x4.trans.shared.b16 {%0,%1,%2,%3}, [%4];" \
                 : "=r"(r0), "=r"(r1), "=r"(r2), "=r"(r3) : "r"(addr))

#define MMA16816(c, a, b0, b1) \
    asm volatile("mma.sync.aligned.m16n8k16.row.col.f32.bf16.bf16.f32 " \
                 "{%0,%1,%2,%3}, {%4,%5,%6,%7}, {%8,%9}, {%0,%1,%2,%3};" \
                 : "+f"((c)[0]), "+f"((c)[1]), "+f"((c)[2]), "+f"((c)[3]) \
                 : "r"((a)[0]), "r"((a)[1]), "r"((a)[2]), "r"((a)[3]), \
                   "r"(b0), "r"(b1))

#define CP16(sm, gp)  asm volatile("cp.async.cg.shared.global [%0], [%1], 16;" :: "r"(sm), "l"(gp))
#define CP_COMMIT()   asm volatile("cp.async.commit_group;" ::: "memory")
#define CP_WAIT(n)    asm volatile("cp.async.wait_group %0;" :: "n"(n) : "memory")

// ---------------- pre-kernel: bf16 hi/lo split of K and V ----------------
__global__ __launch_bounds__(256)
void presplit_kernel(const float* __restrict__ k, const float* __restrict__ v) {
    const float4* k4 = (const float4*)k;
    const float4* v4 = (const float4*)v;
    uint2* kh = (uint2*)g_khi;
    uint2* kl = (uint2*)g_klo;
    uint2* vh = (uint2*)g_vhi;
    uint2* vl = (uint2*)g_vlo;
    const size_t n4 = (size_t)NB * S_LEN * HD / 4;
    for (size_t i = (size_t)blockIdx.x * 256 + threadIdx.x; i < n4;
         i += (size_t)gridDim.x * 256) {
        float4 x = k4[i];
        uint2 H, L;
        split2(x.x, x.y, H.x, L.x);
        split2(x.z, x.w, H.y, L.y);
        kh[i] = H; kl[i] = L;
        x = v4[i];
        split2(x.x, x.y, H.x, L.x);
        split2(x.z, x.w, H.y, L.y);
        vh[i] = H; vl[i] = L;
    }
}

// ---------------- smem layout (shared by full + tail kernels) ----------------
#define COMPB 9216
#define BUFB  (4 * COMPB)        // 36864
#define KH2 0
#define KL2 (1 * COMPB)
#define VH2 (2 * COMPB)
#define VL2 (3 * COMPB)
#define SMEM_TOTAL (2 * BUFB)    // 73728 -> 2 CTAs/SM

__device__ __forceinline__ void issue_tile(uint32_t sbuf,
                                           const uint4* kh, const uint4* kl,
                                           const uint4* vh, const uint4* vl, int tid) {
    #pragma unroll
    for (int i = 0; i < 4; i++) {
        int f = tid + i * 128;                       // 0..511 = row*8 + colgroup
        uint32_t off = (uint32_t)(f >> 3) * 144 + (f & 7) * 16;
        CP16(sbuf + KH2 + off, kh + f);
        CP16(sbuf + KL2 + off, kl + f);
        CP16(sbuf + VH2 + off, vh + f);
        CP16(sbuf + VL2 + off, vl + f);
    }
}

// ---- shared body: stage Q, run KV tiles [T0, T0+NT), leave o/rs in regs ----
// Templated on tile count so both kernels get compile-time loop bounds.
template <int NT>
__device__ __forceinline__ void attention_body(
    const float* __restrict__ q, char* sc, uint32_t sb,
    int b, int q0, int t0,
    float o[2][8][4], float rs[2][2])
{
    const int tid  = threadIdx.x;
    const int lane = tid & 31;
    const int w    = tid >> 5;

    // ---- stage+split Q (two 64-row passes through buffer 0), hoist A-frags ----
    uint32_t qh[2][4][4], ql[2][4][4];
    {
        const float L2E = 1.4426950408889634f;
        #pragma unroll 1
        for (int p = 0; p < 2; p++) {
            const float4* qg4 =
                (const float4*)(q + ((size_t)b * S_LEN + q0 + p * 64) * HD);
            #pragma unroll
            for (int i = 0; i < 4; i++) {
                int f8 = tid + i * 128;
                float4 x = qg4[2 * f8], y = qg4[2 * f8 + 1];
                uint4 H, L;
                split2(x.x * L2E, x.y * L2E, H.x, L.x);
                split2(x.z * L2E, x.w * L2E, H.y, L.y);
                split2(y.x * L2E, y.y * L2E, H.z, L.z);
                split2(y.z * L2E, y.w * L2E, H.w, L.w);
                uint32_t off = (uint32_t)(f8 >> 3) * 144 + (f8 & 7) * 16;
                *(uint4*)(sc + KH2 + off) = H;
                *(uint4*)(sc + KL2 + off) = L;
            }
            __syncthreads();
            if ((w >> 1) == p) {
                const uint32_t aQ = sb + KH2
                    + (uint32_t)((w & 1) * 32 + (lane & 15)) * 144
                    + ((lane >> 4) & 1) * 16;
                #pragma unroll
                for (int g = 0; g < 2; g++)
                    #pragma unroll
                    for (int kc = 0; kc < 4; kc++) {
                        LDSM4(qh[g][kc][0], qh[g][kc][1], qh[g][kc][2], qh[g][kc][3],
                              aQ + g * 16 * 144 + kc * 32);
                        LDSM4(ql[g][kc][0], ql[g][kc][1], ql[g][kc][2], ql[g][kc][3],
                              aQ + COMPB + g * 16 * 144 + kc * 32);
                    }
            }
            __syncthreads();
        }
    }

    const uint4* khB = g_khi + (size_t)b * S_LEN * 8 + (size_t)t0 * 512;
    const uint4* klB = g_klo + (size_t)b * S_LEN * 8 + (size_t)t0 * 512;
    const uint4* vhB = g_vhi + (size_t)b * S_LEN * 8 + (size_t)t0 * 512;
    const uint4* vlB = g_vlo + (size_t)b * S_LEN * 8 + (size_t)t0 * 512;

    issue_tile(sb,        khB,       klB,       vhB,       vlB,       tid);
    CP_COMMIT();
    issue_tile(sb + BUFB, khB + 512, klB + 512, vhB + 512, vlB + 512, tid);
    CP_COMMIT();

    #pragma unroll
    for (int g = 0; g < 2; g++) {
        rs[g][0] = 0.0f; rs[g][1] = 0.0f;
        #pragma unroll
        for (int d = 0; d < 8; d++)
            #pragma unroll
            for (int j = 0; j < 4; j++) o[g][d][j] = 0.0f;
    }

    #pragma unroll 1
    for (int t = 0; t < NT; t++) {
        const uint32_t bufo = (uint32_t)(t & 1) * BUFB;

        CP_WAIT(1);
        __syncthreads();

        const uint32_t bK = sb + bufo + KH2
            + (uint32_t)((lane & 7) + ((lane >> 4) & 1) * 8) * 144
            + ((lane >> 3) & 1) * 16;
        const uint32_t bV = sb + bufo + VH2
            + (uint32_t)((lane & 7) + ((lane >> 3) & 1) * 8) * 144
            + ((lane >> 4) & 1) * 16;

        // ---- S = Q K^T, 3xBF16 ----
        float s[2][8][4];
        #pragma unroll
        for (int g = 0; g < 2; g++)
            #pragma unroll
            for (int np = 0; np < 8; np++)
                #pragma unroll
                for (int j = 0; j < 4; j++) s[g][np][j] = 0.0f;

        #pragma unroll
        for (int kc = 0; kc < 4; kc++)
            #pragma unroll
            for (int grp = 0; grp < 4; grp++) {
                uint32_t bh[4], bl[4];
                LDSM4(bh[0], bh[1], bh[2], bh[3], bK + grp * 2304 + kc * 32);
                LDSM4(bl[0], bl[1], bl[2], bl[3], bK + COMPB + grp * 2304 + kc * 32);
                #pragma unroll
                for (int g = 0; g < 2; g++) {
                    MMA16816(s[g][2*grp],   qh[g][kc], bh[0], bh[1]);
                    MMA16816(s[g][2*grp+1], qh[g][kc], bh[2], bh[3]);
                    MMA16816(s[g][2*grp],   qh[g][kc], bl[0], bl[1]);
                    MMA16816(s[g][2*grp+1], qh[g][kc], bl[2], bl[3]);
                    MMA16816(s[g][2*grp],   ql[g][kc], bh[0], bh[1]);
                    MMA16816(s[g][2*grp+1], ql[g][kc], bh[2], bh[3]);
                }
            }

        // ---- exp + row sums + split (s dies here) ----
        uint32_t ph[2][4][4], pl[2][4][4];
        #pragma unroll
        for (int g = 0; g < 2; g++)
            #pragma unroll
            for (int kc = 0; kc < 4; kc++) {
                float a0 = ex2f(s[g][2*kc][0]),   a1 = ex2f(s[g][2*kc][1]);
                float a2 = ex2f(s[g][2*kc][2]),   a3 = ex2f(s[g][2*kc][3]);
                float b0 = ex2f(s[g][2*kc+1][0]), b1 = ex2f(s[g][2*kc+1][1]);
                float b2 = ex2f(s[g][2*kc+1][2]), b3 = ex2f(s[g][2*kc+1][3]);
                rs[g][0] += a0 + a1 + b0 + b1;
                rs[g][1] += a2 + a3 + b2 + b3;
                split2(a0, a1, ph[g][kc][0], pl[g][kc][0]);
                split2(a2, a3, ph[g][kc][1], pl[g][kc][1]);
                split2(b0, b1, ph[g][kc][2], pl[g][kc][2]);
                split2(b2, b3, ph[g][kc][3], pl[g][kc][3]);
            }

        // ---- O += P V, 3xBF16 ----
        #pragma unroll
        for (int kc = 0; kc < 4; kc++)
            #pragma unroll
            for (int np = 0; np < 4; np++) {
                uint32_t vh[4], vl[4];
                LDSM4T(vh[0], vh[1], vh[2], vh[3], bV + kc * 2304 + np * 32);
                LDSM4T(vl[0], vl[1], vl[2], vl[3], bV + COMPB + kc * 2304 + np * 32);
                #pragma unroll
                for (int g = 0; g < 2; g++) {
                    MMA16816(o[g][2*np],   ph[g][kc], vh[0], vh[1]);
                    MMA16816(o[g][2*np+1], ph[g][kc], vh[2], vh[3]);
                    MMA16816(o[g][2*np],   ph[g][kc], vl[0], vl[1]);
                    MMA16816(o[g][2*np+1], ph[g][kc], vl[2], vl[3]);
                    MMA16816(o[g][2*np],   pl[g][kc], vh[0], vh[1]);
                    MMA16816(o[g][2*np+1], pl[g][kc], vh[2], vh[3]);
                }
            }

        __syncthreads();
        const int tn = (t + 2) & (NT - 1);       // compile-time mask
        issue_tile(sb + bufo, khB + (size_t)tn * 512, klB + (size_t)tn * 512,
                   vhB + (size_t)tn * 512, vlB + (size_t)tn * 512, tid);
        CP_COMMIT();
    }

    CP_WAIT(0);

    // quad-reduce row sums
    #pragma unroll
    for (int g = 0; g < 2; g++)
        #pragma unroll
        for (int j = 0; j < 2; j++) {
            rs[g][j] += __shfl_xor_sync(0xffffffffu, rs[g][j], 1);
            rs[g][j] += __shfl_xor_sync(0xffffffffu, rs[g][j], 2);
        }
}

// ---------------- full kernel: 888 pairs, all 16 KV tiles, direct out ----------------
__global__ __launch_bounds__(128, 2)
void mea_full_kernel(const float* __restrict__ q, float* __restrict__ out) {
    extern __shared__ char sc[];
    const uint32_t sb = smem_u32(sc);
    const int lane = threadIdx.x & 31;
    const int w    = threadIdx.x >> 5;
    const int gid  = lane >> 2;
    const int tig  = lane & 3;
    const int b  = blockIdx.x >> 3;
    const int q0 = (blockIdx.x & 7) * BM;

    float o[2][8][4], rs[2][2];
    attention_body<KTILES>(q, sc, sb, b, q0, 0, o, rs);

    #pragma unroll
    for (int g = 0; g < 2; g++) {
        const float i0 = 1.0f / rs[g][0];
        const float i1 = 1.0f / rs[g][1];
        float* orow = out + ((size_t)b * S_LEN + q0 + w * 32 + g * 16 + gid) * HD;
        #pragma unroll
        for (int d = 0; d < 8; d++) {
            *(float2*)(orow + d * 8 + 2 * tig) =
                make_float2(o[g][d][0] * i0, o[g][d][1] * i0);
            *(float2*)(orow + 8 * HD + d * 8 + 2 * tig) =
                make_float2(o[g][d][2] * i1, o[g][d][3] * i1);
        }
    }
}

// ---------------- tail kernel: 272 half-KV CTAs, write partials ----------------
__global__ __launch_bounds__(128, 2)
void mea_tail_kernel(const float* __restrict__ q) {
    extern __shared__ char sc[];
    const uint32_t sb = smem_u32(sc);
    const int lane = threadIdx.x & 31;
    const int w    = threadIdx.x >> 5;
    const int gid  = lane >> 2;
    const int tig  = lane & 3;
    const int sci = blockIdx.x;                    // 0..271
    const int pid = FULL_CTAS + (sci >> 1);
    const int b  = pid >> 3;
    const int q0 = (pid & 7) * BM;
    const int t0 = (sci & 1) * (KTILES / 2);

    float o[2][8][4], rs[2][2];
    attention_body<KTILES / 2>(q, sc, sb, b, q0, t0, o, rs);

    #pragma unroll
    for (int g = 0; g < 2; g++) {
        float* prow = g_po + ((size_t)sci * BM + w * 32 + g * 16 + gid) * HD;
        #pragma unroll
        for (int d = 0; d < 8; d++) {
            *(float2*)(prow + d * 8 + 2 * tig) = make_float2(o[g][d][0], o[g][d][1]);
            *(float2*)(prow + 8 * HD + d * 8 + 2 * tig) =
                make_float2(o[g][d][2], o[g][d][3]);
        }
        if (tig == 0) {
            g_prs[(size_t)sci * BM + w * 32 + g * 16 + gid]     = rs[g][0];
            g_prs[(size_t)sci * BM + w * 32 + g * 16 + 8 + gid] = rs[g][1];
        }
    }
}

// ---------------- combine kernel: sum split halves, normalize ----------------
__global__ __launch_bounds__(128)
void combine_kernel(float* __restrict__ out) {
    const int i   = blockIdx.x;
    const int row = threadIdx.x;
    const int pid = FULL_CTAS + i;
    const int b   = pid >> 3;
    const int qi  = pid & 7;

    const float rsum = g_prs[(size_t)(2 * i) * BM + row]
                     + g_prs[(size_t)(2 * i + 1) * BM + row];
    const float inv = 1.0f / rsum;

    const float4* p0 = (const float4*)(g_po + ((size_t)(2 * i)     * BM + row) * HD);
    const float4* p1 = (const float4*)(g_po + ((size_t)(2 * i + 1) * BM + row) * HD);
    float4* orow = (float4*)(out + ((size_t)b * S_LEN + qi * BM + row) * HD);
    #pragma unroll
    for (int c = 0; c < HD / 4; c++) {
        float4 a = p0[c], d = p1[c];
        orow[c] = make_float4((a.x + d.x) * inv, (a.y + d.y) * inv,
                              (a.z + d.z) * inv, (a.w + d.w) * inv);
    }
}

// ---------------- launch ----------------
extern "C" void kernel_launch(void* const* d_in, const int* in_sizes, int n_in,
                              void* d_out, int out_size)
{
    const float* q = (const float*)d_in[0];
    const float* k = (const float*)d_in[1];
    const float* v = (const float*)d_in[2];
    float* out = (float*)d_out;

    cudaFuncSetAttribute(mea_full_kernel,
                         cudaFuncAttributeMaxDynamicSharedMemorySize, SMEM_TOTAL);
    cudaFuncSetAttribute(mea_tail_kernel,
                         cudaFuncAttributeMaxDynamicSharedMemorySize, SMEM_TOTAL);

    presplit_kernel<<<2048, 256>>>(k, v);
    mea_full_kernel<<<FULL_CTAS, 128, SMEM_TOTAL>>>(q, out);
    mea_tail_kernel<<<2 * TAIL_PAIRS, 128, SMEM_TOTAL>>>(q);
    combine_kernel<<<TAIL_PAIRS, 128>>>(out);
}